// round 2
// baseline (speedup 1.0000x reference)
#include <cuda_runtime.h>
#include <cuda_bf16.h>

#define N_NODES 100000
#define N_EDGES 1600000
#define DIM 128
#define ODIM 16

// ---------------- static scratch (no allocs allowed) ----------------
__device__ float g_y1[N_NODES * DIM];   // spmm(x)
__device__ float g_y2[N_NODES * DIM];   // spmm(spmm(x))
__device__ int   g_deg[N_NODES];
__device__ int   g_start[N_NODES];
__device__ int   g_pos[N_NODES];
__device__ float g_dinv[N_NODES];
__device__ int   g_csr[N_EDGES];
__device__ int   g_cursor;
__device__ int   g_shift;   // 0 = int32 edge words, 1 = int64 (read low word)

// ---------------- dtype detect + zero ----------------
__global__ void k_zero(const int* __restrict__ eraw) {
    int i = blockIdx.x * blockDim.x + threadIdx.x;
    if (i < N_NODES) g_deg[i] = 0;
    if (i == 0) {
        g_cursor = 0;
        // int64 little-endian: every odd 32-bit word is the (zero) high half.
        // Random int32 node ids make "64 consecutive zero odd words" impossible.
        int is64 = 1;
        for (int e = 0; e < 64; e++) {
            if (eraw[2 * e + 1] != 0) { is64 = 0; break; }
        }
        g_shift = is64;
    }
}

__device__ __forceinline__ int edge_at(const int* __restrict__ eraw, long long pos) {
    return eraw[pos << g_shift];
}

// ---------------- CSR build ----------------
__global__ void k_count(const int* __restrict__ eraw) {
    int e = blockIdx.x * blockDim.x + threadIdx.x;
    if (e < N_EDGES) atomicAdd(&g_deg[edge_at(eraw, e)], 1);
}

__global__ void k_alloc() {
    int i = blockIdx.x * blockDim.x + threadIdx.x;
    if (i < N_NODES) {
        int d = g_deg[i];
        int s = atomicAdd(&g_cursor, d);
        g_start[i] = s;
        g_pos[i]   = s;
        g_dinv[i]  = 1.0f / (float)max(d, 1);
    }
}

__global__ void k_scatter(const int* __restrict__ eraw) {
    int e = blockIdx.x * blockDim.x + threadIdx.x;
    if (e < N_EDGES) {
        int r = edge_at(eraw, e);
        int c = edge_at(eraw, (long long)N_EDGES + e);
        int p = atomicAdd(&g_pos[r], 1);
        g_csr[p] = c;
    }
}

// ---------------- SpMM: y[i,:] = sum_{j in adj(i)} v[j,:] ----------------
// one warp per node, float4 per lane (32*16B = full 512B row per iteration)
__global__ void k_spmm(const float4* __restrict__ vin, float4* __restrict__ vout) {
    int node = blockIdx.x * blockDim.y + threadIdx.y;
    if (node >= N_NODES) return;
    int lane = threadIdx.x;
    int s = g_start[node];
    int d = g_deg[node];
    float4 acc = make_float4(0.f, 0.f, 0.f, 0.f);
    #pragma unroll 4
    for (int k = 0; k < d; k++) {
        int c = __ldg(&g_csr[s + k]);
        float4 v = __ldg(&vin[c * 32 + lane]);
        acc.x += v.x; acc.y += v.y; acc.z += v.z; acc.w += v.w;
    }
    vout[node * 32 + lane] = acc;
}

// ---------------- fused 3-branch MLP + classifier ----------------
// per CTA: 128 nodes. For each branch b in {ego, h1, h2}:
//   stage1: H = relu(scale_b * (A_b @ W_b) + bias_b)   (128x128, reg-tiled 8x8)
//   stage2: out += H @ Wc[b]                           (128x16, via smem Ht)
#define SM_AS   0                      // As[16][128]  transposed A tile (8KB)
#define SM_BS   8192                   // Bs[16][128]  W tile            (8KB)
#define SM_HT   16384                  // Ht[128][132] H transposed      (66KB)
#define SM_WCS  83968                  // Wcs[128][16]                   (8KB)
#define SM_TOTAL 92160

__global__ __launch_bounds__(256, 2)
void k_mlp(const float* __restrict__ x,
           const float* __restrict__ y1v,
           const float* __restrict__ y2v,
           const float* __restrict__ Wego, const float* __restrict__ bego,
           const float* __restrict__ W1,   const float* __restrict__ b1,
           const float* __restrict__ W2,   const float* __restrict__ b2,
           const float* __restrict__ Wc,   const float* __restrict__ bc,
           float* __restrict__ out) {
    extern __shared__ char smem_raw[];
    float* As  = (float*)(smem_raw + SM_AS);    // [16][128]
    float* Bs  = (float*)(smem_raw + SM_BS);    // [16][128]
    float* Ht  = (float*)(smem_raw + SM_HT);    // [128][132]
    float* Wcs = (float*)(smem_raw + SM_WCS);   // [128][16]

    const int tid = threadIdx.x;
    const int m0  = blockIdx.x * 128;
    const int rg  = tid & 15, cg = tid >> 4;
    const int r0  = rg * 8, c0 = cg * 8;       // stage1: rows r0.., cols c0..
    const int oc  = tid & 15;                  // stage2: output column
    const int nb  = (tid >> 4) * 8;            // stage2: node group base

    float oacc[8];
    #pragma unroll
    for (int i = 0; i < 8; i++) oacc[i] = 0.f;

    for (int br = 0; br < 3; br++) {
        const float* A    = (br == 0) ? x    : (br == 1 ? y1v : y2v);
        const float* W    = (br == 0) ? Wego : (br == 1 ? W1  : W2);
        const float* bias = (br == 0) ? bego : (br == 1 ? b1  : b2);

        // load this branch's classifier slice (contiguous 2048 floats)
        #pragma unroll
        for (int p = 0; p < 2; p++) {
            int t = tid + 256 * p;
            ((float4*)Wcs)[t] = __ldg(&((const float4*)(Wc + br * 128 * 16))[t]);
        }

        float acc[8][8];
        #pragma unroll
        for (int i = 0; i < 8; i++)
            #pragma unroll
            for (int j = 0; j < 8; j++) acc[i][j] = 0.f;

        for (int k0 = 0; k0 < 128; k0 += 16) {
            // A tile -> As[k][m] (transposed)
            #pragma unroll
            for (int p = 0; p < 2; p++) {
                int t = tid + 256 * p;       // 0..511
                int m = t >> 2;              // 0..127
                int kq = (t & 3) * 4;
                float4 v = make_float4(0.f, 0.f, 0.f, 0.f);
                if (m0 + m < N_NODES)
                    v = __ldg((const float4*)&A[(size_t)(m0 + m) * 128 + k0 + kq]);
                As[(kq + 0) * 128 + m] = v.x;
                As[(kq + 1) * 128 + m] = v.y;
                As[(kq + 2) * 128 + m] = v.z;
                As[(kq + 3) * 128 + m] = v.w;
            }
            // W tile -> Bs[k][n]
            #pragma unroll
            for (int p = 0; p < 2; p++) {
                int t = tid + 256 * p;
                int kk = t >> 5;             // 0..15
                int nq = (t & 31) * 4;
                *(float4*)&Bs[kk * 128 + nq] =
                    __ldg((const float4*)&W[(k0 + kk) * 128 + nq]);
            }
            __syncthreads();
            #pragma unroll
            for (int kk = 0; kk < 16; kk++) {
                float4 a0 = *(const float4*)&As[kk * 128 + r0];
                float4 a1 = *(const float4*)&As[kk * 128 + r0 + 4];
                float4 b0 = *(const float4*)&Bs[kk * 128 + c0];
                float4 b1 = *(const float4*)&Bs[kk * 128 + c0 + 4];
                float av[8] = {a0.x, a0.y, a0.z, a0.w, a1.x, a1.y, a1.z, a1.w};
                float bv[8] = {b0.x, b0.y, b0.z, b0.w, b1.x, b1.y, b1.z, b1.w};
                #pragma unroll
                for (int i = 0; i < 8; i++)
                    #pragma unroll
                    for (int j = 0; j < 8; j++)
                        acc[i][j] += bv[i] * av[j];
            }
            __syncthreads();
        }

        // epilogue stage1: scale + bias + relu -> Ht[col][row] (transposed, pad 132)
        float sc[8];
        #pragma unroll
        for (int j = 0; j < 8; j++) {
            int m = m0 + r0 + j;
            if (br == 0) sc[j] = 1.f;
            else {
                float di = (m < N_NODES) ? g_dinv[m] : 1.f;
                sc[j] = (br == 1) ? di : di * di;
            }
        }
        #pragma unroll
        for (int i = 0; i < 8; i++) {
            float bv = __ldg(&bias[c0 + i]);
            float4 h0, h1;
            h0.x = fmaxf(acc[i][0] * sc[0] + bv, 0.f);
            h0.y = fmaxf(acc[i][1] * sc[1] + bv, 0.f);
            h0.z = fmaxf(acc[i][2] * sc[2] + bv, 0.f);
            h0.w = fmaxf(acc[i][3] * sc[3] + bv, 0.f);
            h1.x = fmaxf(acc[i][4] * sc[4] + bv, 0.f);
            h1.y = fmaxf(acc[i][5] * sc[5] + bv, 0.f);
            h1.z = fmaxf(acc[i][6] * sc[6] + bv, 0.f);
            h1.w = fmaxf(acc[i][7] * sc[7] + bv, 0.f);
            *(float4*)&Ht[(c0 + i) * 132 + r0]     = h0;
            *(float4*)&Ht[(c0 + i) * 132 + r0 + 4] = h1;
        }
        __syncthreads();

        // stage2: out[nb..nb+8][oc] += H @ Wc_br  (read Ht[c][node] vectorized)
        #pragma unroll 8
        for (int c = 0; c < 128; c++) {
            float w = Wcs[c * 16 + oc];
            float4 h0 = *(const float4*)&Ht[c * 132 + nb];
            float4 h1 = *(const float4*)&Ht[c * 132 + nb + 4];
            oacc[0] += h0.x * w; oacc[1] += h0.y * w;
            oacc[2] += h0.z * w; oacc[3] += h0.w * w;
            oacc[4] += h1.x * w; oacc[5] += h1.y * w;
            oacc[6] += h1.z * w; oacc[7] += h1.w * w;
        }
        __syncthreads();
    }

    float bcv = __ldg(&bc[oc]);
    #pragma unroll
    for (int i = 0; i < 8; i++) {
        int node = m0 + nb + i;
        if (node < N_NODES) out[node * 16 + oc] = oacc[i] + bcv;
    }
}

// ---------------- launch ----------------
extern "C" void kernel_launch(void* const* d_in, const int* in_sizes, int n_in,
                              void* d_out, int out_size) {
    const float* x    = (const float*)d_in[0];
    const int*   ei   = (const int*)d_in[1];   // int32 words (or int64 pairs; detected)
    const float* Wego = (const float*)d_in[2];
    const float* bego = (const float*)d_in[3];
    const float* W1   = (const float*)d_in[4];
    const float* b1   = (const float*)d_in[5];
    const float* W2   = (const float*)d_in[6];
    const float* b2   = (const float*)d_in[7];
    const float* Wc   = (const float*)d_in[8];
    const float* bc   = (const float*)d_in[9];
    float*       out  = (float*)d_out;

    void *py1 = nullptr, *py2 = nullptr;
    cudaGetSymbolAddress(&py1, g_y1);
    cudaGetSymbolAddress(&py2, g_y2);

    cudaFuncSetAttribute(k_mlp, cudaFuncAttributeMaxDynamicSharedMemorySize, SM_TOTAL);

    k_zero<<<(N_NODES + 1023) / 1024, 1024>>>(ei);
    k_count<<<(N_EDGES + 255) / 256, 256>>>(ei);
    k_alloc<<<(N_NODES + 255) / 256, 256>>>();
    k_scatter<<<(N_EDGES + 255) / 256, 256>>>(ei);

    dim3 sb(32, 4);
    k_spmm<<<(N_NODES + 3) / 4, sb>>>((const float4*)x, (float4*)py1);
    k_spmm<<<(N_NODES + 3) / 4, sb>>>((const float4*)py1, (float4*)py2);

    k_mlp<<<(N_NODES + 127) / 128, 256, SM_TOTAL>>>(
        x, (const float*)py1, (const float*)py2,
        Wego, bego, W1, b1, W2, b2, Wc, bc, out);
}

// round 3
// speedup vs baseline: 1.1064x; 1.1064x over previous
#include <cuda_runtime.h>
#include <cuda_bf16.h>
#include <mma.h>

using namespace nvcuda;

#define N_NODES 100000
#define N_EDGES 1600000
#define DIM 128
#define ODIM 16

// ---------------- static scratch (no allocs allowed) ----------------
__device__ float g_y1[N_NODES * DIM];   // spmm(x)
__device__ float g_y2[N_NODES * DIM];   // spmm(spmm(x))
__device__ int   g_deg[N_NODES];
__device__ int   g_start[N_NODES];
__device__ int   g_pos[N_NODES];
__device__ float g_dinv[N_NODES];
__device__ int   g_csr[N_EDGES];
__device__ int   g_cursor;
__device__ int   g_shift;   // 0 = int32 edge words, 1 = int64 (read low word)

// ---------------- dtype detect + zero ----------------
__global__ void k_zero(const int* __restrict__ eraw) {
    int i = blockIdx.x * blockDim.x + threadIdx.x;
    if (i < N_NODES) g_deg[i] = 0;
    if (i == 0) {
        g_cursor = 0;
        int is64 = 1;
        for (int e = 0; e < 64; e++) {
            if (eraw[2 * e + 1] != 0) { is64 = 0; break; }
        }
        g_shift = is64;
    }
}

__device__ __forceinline__ int edge_at(const int* __restrict__ eraw, long long pos) {
    return eraw[pos << g_shift];
}

// ---------------- CSR build ----------------
__global__ void k_count(const int* __restrict__ eraw) {
    int e = blockIdx.x * blockDim.x + threadIdx.x;
    if (e < N_EDGES) atomicAdd(&g_deg[edge_at(eraw, e)], 1);
}

__global__ void k_alloc() {
    int i = blockIdx.x * blockDim.x + threadIdx.x;
    if (i < N_NODES) {
        int d = g_deg[i];
        int s = atomicAdd(&g_cursor, d);
        g_start[i] = s;
        g_pos[i]   = s;
        g_dinv[i]  = 1.0f / (float)max(d, 1);
    }
}

__global__ void k_scatter(const int* __restrict__ eraw) {
    int e = blockIdx.x * blockDim.x + threadIdx.x;
    if (e < N_EDGES) {
        int r = edge_at(eraw, e);
        int c = edge_at(eraw, (long long)N_EDGES + e);
        int p = atomicAdd(&g_pos[r], 1);
        g_csr[p] = c;
    }
}

// ---------------- SpMM: y[i,:] = sum_{j in adj(i)} v[j,:] ----------------
__global__ void k_spmm(const float4* __restrict__ vin, float4* __restrict__ vout) {
    int node = blockIdx.x * blockDim.y + threadIdx.y;
    if (node >= N_NODES) return;
    int lane = threadIdx.x;
    int s = g_start[node];
    int d = g_deg[node];
    float4 acc = make_float4(0.f, 0.f, 0.f, 0.f);
    #pragma unroll 4
    for (int k = 0; k < d; k++) {
        int c = __ldg(&g_csr[s + k]);
        float4 v = __ldg(&vin[c * 32 + lane]);
        acc.x += v.x; acc.y += v.y; acc.z += v.z; acc.w += v.w;
    }
    vout[node * 32 + lane] = acc;
}

// ---------------- fused 3-branch MLP + classifier (tf32 WMMA stage1) ------
// per CTA: 128 nodes. smem buffer S [128][136] holds A tile during the K loop,
// then is reused as col-major H^T [n=128][m=136-stride] for the epilogue.
#define LDS_T 136
#define SM_S     0                              // 128*136*4 = 69632
#define SM_WCS   69632                          // 2048*4    = 8192
#define SM_BIAS  77824                          // 128*4     = 512
#define SM_DSC   78336                          // 128*4     = 512
#define SM_TOTAL 78848

__global__ __launch_bounds__(256, 2)
void k_mlp(const float* __restrict__ x,
           const float* __restrict__ y1v,
           const float* __restrict__ y2v,
           const float* __restrict__ Wego, const float* __restrict__ bego,
           const float* __restrict__ W1,   const float* __restrict__ b1,
           const float* __restrict__ W2,   const float* __restrict__ b2,
           const float* __restrict__ Wc,   const float* __restrict__ bc,
           float* __restrict__ out) {
    extern __shared__ char smem_raw[];
    float* S      = (float*)(smem_raw + SM_S);     // A tile / Ht (reused)
    float* Wcs    = (float*)(smem_raw + SM_WCS);   // [128][16]
    float* bias_s = (float*)(smem_raw + SM_BIAS);  // [128]
    float* dsc    = (float*)(smem_raw + SM_DSC);   // [128] per-node scale

    const int tid = threadIdx.x;
    const int m0  = blockIdx.x * 128;
    const int wid = tid >> 5;
    const int wm  = wid & 3;          // 4 warps over M (32 rows each)
    const int wn  = wid >> 2;         // 2 warps over N (64 cols each)
    const int mrow0 = wm * 32;
    const int ncol0 = wn * 64;

    const int oc = tid & 15;          // stage2: output column
    const int nb = (tid >> 4) * 8;    // stage2: node group base

    float oacc[8];
    #pragma unroll
    for (int i = 0; i < 8; i++) oacc[i] = 0.f;

    for (int br = 0; br < 3; br++) {
        const float* A    = (br == 0) ? x    : (br == 1 ? y1v : y2v);
        const float* W    = (br == 0) ? Wego : (br == 1 ? W1  : W2);
        const float* bias = (br == 0) ? bego : (br == 1 ? b1  : b2);

        // small per-branch constants into smem
        #pragma unroll
        for (int p = 0; p < 2; p++) {
            int t = tid + 256 * p;
            ((float4*)Wcs)[t] = __ldg(&((const float4*)(Wc + br * 128 * 16))[t]);
        }
        if (tid < 128) {
            bias_s[tid] = __ldg(&bias[tid]);
            int m = m0 + tid;
            float di = (m < N_NODES) ? g_dinv[m] : 1.f;
            dsc[tid] = (br == 0) ? 1.f : ((br == 1) ? di : di * di);
        }

        // stage A tile: 128 rows x 128 cols -> S row-major ld=136
        {
            int m    = tid >> 1;
            int half = (tid & 1) * 64;
            bool ok  = (m0 + m) < N_NODES;
            const float4* src = (const float4*)&A[(size_t)(m0 + m) * 128 + half];
            float4* dst = (float4*)&S[m * LDS_T + half];
            #pragma unroll
            for (int q = 0; q < 16; q++) {
                float4 v = ok ? __ldg(&src[q]) : make_float4(0.f, 0.f, 0.f, 0.f);
                dst[q] = v;
            }
        }
        __syncthreads();

        // K loop: tf32 WMMA, each warp computes 32x64
        wmma::fragment<wmma::accumulator, 16, 16, 8, float> acc[2][4];
        #pragma unroll
        for (int i = 0; i < 2; i++)
            #pragma unroll
            for (int j = 0; j < 4; j++) wmma::fill_fragment(acc[i][j], 0.f);

        #pragma unroll 4
        for (int k0 = 0; k0 < 128; k0 += 8) {
            wmma::fragment<wmma::matrix_a, 16, 16, 8, wmma::precision::tf32,
                           wmma::row_major> af[2];
            #pragma unroll
            for (int i = 0; i < 2; i++) {
                wmma::load_matrix_sync(af[i], S + (mrow0 + i * 16) * LDS_T + k0, LDS_T);
                #pragma unroll
                for (int e = 0; e < af[i].num_elements; e++)
                    af[i].x[e] = wmma::__float_to_tf32(af[i].x[e]);
            }
            wmma::fragment<wmma::matrix_b, 16, 16, 8, wmma::precision::tf32,
                           wmma::row_major> bf[4];
            #pragma unroll
            for (int j = 0; j < 4; j++) {
                wmma::load_matrix_sync(bf[j], W + k0 * 128 + ncol0 + j * 16, 128);
                #pragma unroll
                for (int e = 0; e < bf[j].num_elements; e++)
                    bf[j].x[e] = wmma::__float_to_tf32(bf[j].x[e]);
            }
            #pragma unroll
            for (int i = 0; i < 2; i++)
                #pragma unroll
                for (int j = 0; j < 4; j++)
                    wmma::mma_sync(acc[i][j], af[i], bf[j], acc[i][j]);
        }
        __syncthreads();   // everyone done reading S (A tile)

        // store raw acc col-major into S reused as Ht[n][m], ld=136
        #pragma unroll
        for (int i = 0; i < 2; i++)
            #pragma unroll
            for (int j = 0; j < 4; j++)
                wmma::store_matrix_sync(
                    S + (ncol0 + j * 16) * LDS_T + (mrow0 + i * 16),
                    acc[i][j], LDS_T, wmma::mem_col_major);
        __syncthreads();

        // fixup: h = relu(acc * dsc[m] + bias[c]) in place
        {
            int c  = tid >> 1;
            int mh = (tid & 1) * 64;
            float bb = bias_s[c];
            #pragma unroll
            for (int q = 0; q < 16; q++) {
                int m = mh + q * 4;
                float4 v = *(float4*)&S[c * LDS_T + m];
                float4 dv = *(const float4*)&dsc[m];
                v.x = fmaxf(fmaf(v.x, dv.x, bb), 0.f);
                v.y = fmaxf(fmaf(v.y, dv.y, bb), 0.f);
                v.z = fmaxf(fmaf(v.z, dv.z, bb), 0.f);
                v.w = fmaxf(fmaf(v.w, dv.w, bb), 0.f);
                *(float4*)&S[c * LDS_T + m] = v;
            }
        }
        __syncthreads();

        // stage2: out[nb..nb+8][oc] += H @ Wc_br
        #pragma unroll 8
        for (int c = 0; c < 128; c++) {
            float w = Wcs[c * 16 + oc];
            float4 h0 = *(const float4*)&S[c * LDS_T + nb];
            float4 h1 = *(const float4*)&S[c * LDS_T + nb + 4];
            oacc[0] += h0.x * w; oacc[1] += h0.y * w;
            oacc[2] += h0.z * w; oacc[3] += h0.w * w;
            oacc[4] += h1.x * w; oacc[5] += h1.y * w;
            oacc[6] += h1.z * w; oacc[7] += h1.w * w;
        }
        __syncthreads();
    }

    float bcv = __ldg(&bc[oc]);
    #pragma unroll
    for (int i = 0; i < 8; i++) {
        int node = m0 + nb + i;
        if (node < N_NODES) out[node * 16 + oc] = oacc[i] + bcv;
    }
}

// ---------------- launch ----------------
extern "C" void kernel_launch(void* const* d_in, const int* in_sizes, int n_in,
                              void* d_out, int out_size) {
    const float* x    = (const float*)d_in[0];
    const int*   ei   = (const int*)d_in[1];
    const float* Wego = (const float*)d_in[2];
    const float* bego = (const float*)d_in[3];
    const float* W1   = (const float*)d_in[4];
    const float* b1   = (const float*)d_in[5];
    const float* W2   = (const float*)d_in[6];
    const float* b2   = (const float*)d_in[7];
    const float* Wc   = (const float*)d_in[8];
    const float* bc   = (const float*)d_in[9];
    float*       out  = (float*)d_out;

    void *py1 = nullptr, *py2 = nullptr;
    cudaGetSymbolAddress(&py1, g_y1);
    cudaGetSymbolAddress(&py2, g_y2);

    cudaFuncSetAttribute(k_mlp, cudaFuncAttributeMaxDynamicSharedMemorySize, SM_TOTAL);

    k_zero<<<(N_NODES + 1023) / 1024, 1024>>>(ei);
    k_count<<<(N_EDGES + 255) / 256, 256>>>(ei);
    k_alloc<<<(N_NODES + 255) / 256, 256>>>();
    k_scatter<<<(N_EDGES + 255) / 256, 256>>>(ei);

    dim3 sb(32, 4);
    k_spmm<<<(N_NODES + 3) / 4, sb>>>((const float4*)x, (float4*)py1);
    k_spmm<<<(N_NODES + 3) / 4, sb>>>((const float4*)py1, (float4*)py2);

    k_mlp<<<(N_NODES + 127) / 128, 256, SM_TOTAL>>>(
        x, (const float*)py1, (const float*)py2,
        Wego, bego, W1, b1, W2, b2, Wc, bc, out);
}